// round 2
// baseline (speedup 1.0000x reference)
#include <cuda_runtime.h>
#include <cstdint>

// Problem constants (shapes fixed by the dataset)
#define NBATCH 2
#define FDIM   128
#define NMAX   50000

// Scratch (device globals; no allocation allowed)
__device__ float g_deg[NMAX];
__device__ float g_dinv[NMAX];
__device__ float g_xlin[(size_t)NBATCH * NMAX * FDIM];   // 51.2 MB
__device__ float g_Wt[FDIM * FDIM];                      // W transposed: [f][o]

// ---------------------------------------------------------------- K0: deg = 1 (self loop)
__global__ void k_init_deg(int N) {
    int i = blockIdx.x * blockDim.x + threadIdx.x;
    if (i < N) g_deg[i] = 1.0f;
}

// ---------------------------------------------------------------- K1: deg[row[e]] += w[e]
__global__ void k_deg(const int* __restrict__ ei, const float* __restrict__ ea, int E) {
    int e = blockIdx.x * blockDim.x + threadIdx.x;
    if (e < E) {
        int r = ei[e];                      // edge_index row e (int32!)
        atomicAdd(&g_deg[r], ea[e]);
    }
}

// ---------------------------------------------------------------- K2: dinv = rsqrt(deg)
__global__ void k_dinv(int N) {
    int i = blockIdx.x * blockDim.x + threadIdx.x;
    if (i < N) {
        float d = g_deg[i];
        g_dinv[i] = (d > 0.0f) ? rsqrtf(d) : 0.0f;
    }
}

// ---------------------------------------------------------------- K3: Wt[f][o] = W[o][f]
__global__ void k_wt(const float* __restrict__ W) {
    int i = blockIdx.x * blockDim.x + threadIdx.x;   // i = f*128 + o
    if (i < FDIM * FDIM) {
        int f = i >> 7, o = i & 127;
        g_Wt[i] = W[o * FDIM + f];
    }
}

// ---------------------------------------------------------------- K4: GEMM + self-loop init of out
// x_lin[rr][o] = sum_f x[rr][f] * W[o][f] + bias[o]      (rr = b*N + n, 0..2N-1)
// out[rr][o]   = dinv[n]^2 * x_lin[rr][o]
// Block: 256 threads, 64 rows/block. tx = tid&31 -> outputs 4*tx..4*tx+3; ty = tid>>5 -> rows ty*8..+7
#define GEMM_ROWS 64
__global__ void k_gemm(const float* __restrict__ x, const float* __restrict__ bias,
                       float* __restrict__ out, int N) {
    extern __shared__ float sm[];
    float* Ws = sm;                      // [128][128] (row = f; LDS.128 by lane -> conflict-free)
    float* xs = sm + FDIM * FDIM;        // [64][128]
    const int tid = threadIdx.x;
    const int BN = NBATCH * N;
    const int row0 = blockIdx.x * GEMM_ROWS;

    // Load transposed W into smem (g_Wt is [f][o] contiguous: coalesced, conflict-free)
    for (int i = tid; i < FDIM * FDIM; i += 256)
        Ws[i] = g_Wt[i];

    // Load 64 rows of x (guard tail block)
    for (int i = tid; i < GEMM_ROWS * FDIM; i += 256) {
        int gr = row0 + (i >> 7);
        xs[i] = (gr < BN) ? x[(size_t)gr * FDIM + (i & 127)] : 0.0f;
    }
    __syncthreads();

    const int tx = tid & 31;
    const int ty = tid >> 5;
    float acc[8][4];
    const float4 b4 = *(const float4*)(bias + 4 * tx);
#pragma unroll
    for (int r = 0; r < 8; r++) {
        acc[r][0] = b4.x; acc[r][1] = b4.y; acc[r][2] = b4.z; acc[r][3] = b4.w;
    }

#pragma unroll 4
    for (int f = 0; f < FDIM; f++) {
        float4 wv = *(const float4*)&Ws[f * FDIM + 4 * tx];
#pragma unroll
        for (int r = 0; r < 8; r++) {
            float xv = xs[(ty * 8 + r) * FDIM + f];
            acc[r][0] = fmaf(xv, wv.x, acc[r][0]);
            acc[r][1] = fmaf(xv, wv.y, acc[r][1]);
            acc[r][2] = fmaf(xv, wv.z, acc[r][2]);
            acc[r][3] = fmaf(xv, wv.w, acc[r][3]);
        }
    }

    // Store x_lin and self-loop-initialized out
#pragma unroll
    for (int r = 0; r < 8; r++) {
        int rr = row0 + ty * 8 + r;
        if (rr < BN) {
            int n = (rr >= N) ? (rr - N) : rr;
            float di = g_dinv[n];
            float sn = di * di;
            float4 v = make_float4(acc[r][0], acc[r][1], acc[r][2], acc[r][3]);
            ((float4*)g_xlin)[(size_t)rr * 32 + tx] = v;
            float4 o = make_float4(sn * v.x, sn * v.y, sn * v.z, sn * v.w);
            ((float4*)out)[(size_t)rr * 32 + tx] = o;
        }
    }
}

// ---------------------------------------------------------------- K5: edge scatter (warp per edge)
// out[b, row, :] += dinv[row]*w*dinv[col] * x_lin[b, col, :]
__global__ void k_scatter(const int* __restrict__ ei, const float* __restrict__ ea,
                          float* __restrict__ out, int N, int E) {
    int w = (blockIdx.x * blockDim.x + threadIdx.x) >> 5;
    int lane = threadIdx.x & 31;
    if (w >= E) return;
    int r = ei[w];          // row
    int c = ei[E + w];      // col
    float norm = g_dinv[r] * ea[w] * g_dinv[c];
    const float4* xl = (const float4*)g_xlin;
    float4* o4 = (float4*)out;
#pragma unroll
    for (int b = 0; b < NBATCH; b++) {
        size_t src = ((size_t)b * N + c) * 32 + lane;
        size_t dst = ((size_t)b * N + r) * 32 + lane;
        float4 v = xl[src];
        float mx = norm * v.x, my = norm * v.y, mz = norm * v.z, mw = norm * v.w;
        asm volatile("red.global.add.v4.f32 [%0], {%1,%2,%3,%4};"
                     :: "l"(o4 + dst), "f"(mx), "f"(my), "f"(mz), "f"(mw)
                     : "memory");
    }
}

// ---------------------------------------------------------------- K6: ReLU in place
__global__ void k_relu(float* __restrict__ out, int n4) {
    int i = blockIdx.x * blockDim.x + threadIdx.x;
    if (i < n4) {
        float4 v = ((float4*)out)[i];
        v.x = fmaxf(v.x, 0.0f);
        v.y = fmaxf(v.y, 0.0f);
        v.z = fmaxf(v.z, 0.0f);
        v.w = fmaxf(v.w, 0.0f);
        ((float4*)out)[i] = v;
    }
}

// ---------------------------------------------------------------- launch
extern "C" void kernel_launch(void* const* d_in, const int* in_sizes, int n_in,
                              void* d_out, int out_size) {
    const float* x    = (const float*)d_in[0];
    const int*   ei   = (const int*)d_in[1];     // int32! (JAX x64 disabled)
    const float* ea   = (const float*)d_in[2];
    const float* W    = (const float*)d_in[3];
    const float* bias = (const float*)d_in[4];
    float*       out  = (float*)d_out;

    const int E  = in_sizes[2];                    // 800000 (edge_attr count)
    const int N  = in_sizes[0] / (NBATCH * FDIM);  // 50000
    const int BN = NBATCH * N;

    k_init_deg<<<(N + 255) / 256, 256>>>(N);
    k_deg<<<(E + 255) / 256, 256>>>(ei, ea, E);
    k_dinv<<<(N + 255) / 256, 256>>>(N);
    k_wt<<<(FDIM * FDIM + 255) / 256, 256>>>(W);

    int smem = (FDIM * FDIM + GEMM_ROWS * FDIM) * (int)sizeof(float);  // 96 KB
    cudaFuncSetAttribute(k_gemm, cudaFuncAttributeMaxDynamicSharedMemorySize, smem);
    k_gemm<<<(BN + GEMM_ROWS - 1) / GEMM_ROWS, 256, smem>>>(x, bias, out, N);

    k_scatter<<<(E * 32 + 255) / 256, 256>>>(ei, ea, out, N, E);
    k_relu<<<(BN * 32 + 255) / 256, 256>>>(out, BN * 32);
}